// round 14
// baseline (speedup 1.0000x reference)
#include <cuda_runtime.h>
#include <cuda_fp16.h>
#include <cstdint>

#define SQ      4096
#define DD      64
#define QT      128          // q rows per CTA
#define KT      64           // keys per tile
#define NT      128          // threads (4 warps x 32 q rows)
#define NTILES  (SQ / KT)    // 64
#define NPAIRS  (NTILES / 2) // 32
#define BB      8

// fp16 scratch (converted once per launch by prologue kernel)
__device__ __half g_Kh[(size_t)BB * SQ * DD];   // [b][s][d]
__device__ __half g_Vt[(size_t)BB * DD * SQ];   // [b][d][s]  (transposed)

#define SCALE (0.125f * 1.44269504088896340736f)   // 1/sqrt(64) * log2(e)

#define RPAD  36                 // tile row: 64 halfs = 32 words + 4 pad
#define SLOTW (KT * RPAD)        // 2304 words per K (or V) slot
#define NSLOT 6
#define SMEM_BYTES (2 * NSLOT * SLOTW * 4)   // 110592

__device__ __forceinline__ uint32_t s2u(const void* p) {
    uint32_t a;
    asm("{ .reg .u64 t; cvta.to.shared.u64 t, %1; cvt.u32.u64 %0, t; }" : "=r"(a) : "l"(p));
    return a;
}
__device__ __forceinline__ void cp16(uint32_t d, const void* s) {
    asm volatile("cp.async.cg.shared.global [%0], [%1], 16;" :: "r"(d), "l"(s));
}
#define CP_COMMIT() asm volatile("cp.async.commit_group;" ::: "memory")
#define CP_WAIT(n)  asm volatile("cp.async.wait_group %0;" :: "n"(n) : "memory")

__device__ __forceinline__ float ex2(float x) {
    float r;
    asm("ex2.approx.ftz.f32 %0, %1;" : "=f"(r) : "f"(x));
    return r;
}
__device__ __forceinline__ uint32_t pk(float p0, float p1) {
    uint32_t r;
    asm("cvt.rn.f16x2.f32 %0, %1, %2;" : "=r"(r) : "f"(p1), "f"(p0));
    return r;
}
__device__ __forceinline__ void mma_f16(float* c, uint32_t a0, uint32_t a1, uint32_t a2,
                                        uint32_t a3, uint32_t b0, uint32_t b1) {
    asm volatile(
        "mma.sync.aligned.m16n8k16.row.col.f32.f16.f16.f32 "
        "{%0,%1,%2,%3}, {%4,%5,%6,%7}, {%8,%9}, {%0,%1,%2,%3};"
        : "+f"(c[0]), "+f"(c[1]), "+f"(c[2]), "+f"(c[3])
        : "r"(a0), "r"(a1), "r"(a2), "r"(a3), "r"(b0), "r"(b1));
}

// ---- prologue: K convert + V transpose ----
#define NKC (BB * SQ * DD / 4 / 256)        // 2048 blocks: K convert
#define NVT (BB * (SQ / 64))                // 512 blocks: V transpose

__global__ void __launch_bounds__(256)
cvt_all(const float* __restrict__ K, const float* __restrict__ V) {
    if (blockIdx.x < NKC) {
        int i = blockIdx.x * 256 + threadIdx.x;       // float4 index
        float4 k = ((const float4*)K)[i];
        __half2* ko = (__half2*)g_Kh;
        ko[2 * i]     = __floats2half2_rn(k.x, k.y);
        ko[2 * i + 1] = __floats2half2_rn(k.z, k.w);
        return;
    }
    // ---- V transpose tile: batch b, s-range [s0, s0+64) ----
    __shared__ float tl[64][65];
    const int vb  = blockIdx.x - NKC;
    const int b   = vb >> 6;
    const int s0  = (vb & 63) * 64;
    const int tid = threadIdx.x;

    const float* src = V + ((size_t)b * SQ + s0) * DD;
    #pragma unroll
    for (int i = 0; i < 16; i++) {
        int idx = tid + i * 256;
        tl[idx >> 6][idx & 63] = src[idx];            // coalesced read
    }
    __syncthreads();

    __half* dst = g_Vt + (size_t)b * DD * SQ + s0;
    #pragma unroll
    for (int i = 0; i < 2; i++) {
        int c  = tid + i * 256;
        int d  = c >> 3;
        int sc = (c & 7) * 8;
        __half h[8];
        #pragma unroll
        for (int j = 0; j < 8; j++) h[j] = __float2half_rn(tl[sc + j][d]);
        *(uint4*)(dst + (size_t)d * SQ + sc) = *(uint4*)h;   // coalesced 16B write
    }
}

__global__ void __launch_bounds__(NT, 2)
attn_mma(const float* __restrict__ Qf, const float* __restrict__ Mask,
         float* __restrict__ O) {
    extern __shared__ uint32_t smw[];
    uint32_t* Ks = smw;                    // NSLOT x SLOTW
    uint32_t* Vs = smw + NSLOT * SLOTW;    // NSLOT x SLOTW

    const int tid  = threadIdx.x;
    const int w    = tid >> 5;
    const int lane = tid & 31;
    const int g    = lane >> 2;
    const int q    = lane & 3;

    const int b  = blockIdx.y;
    const int qb = blockIdx.x * QT;
    const __half* Kg = g_Kh + (size_t)b * SQ * DD;
    const __half* Vg = g_Vt + (size_t)b * DD * SQ;

    const uint32_t ks_u = s2u(Ks);
    const uint32_t vs_u = s2u(Vs);

    auto load_kv = [&](int tile) {
        const int slot = tile % NSLOT;
        const __half* kt = Kg + (size_t)tile * KT * DD;
        const __half* vt = Vg + tile * KT;            // V row stride SQ
        #pragma unroll
        for (int i = 0; i < 8; i++) {
            int c = tid + i * NT;                     // 0..1023
            if (c < 512) {                            // K: 64 rows x 8 chunks
                int row = c >> 3, sub = c & 7;
                cp16(ks_u + (uint32_t)(slot * SLOTW + row * RPAD + sub * 4) * 4,
                     kt + row * DD + sub * 8);
            } else {                                  // V: 64 rows x 8 chunks
                int c2 = c - 512;
                int row = c2 >> 3, sub = c2 & 7;
                cp16(vs_u + (uint32_t)(slot * SLOTW + row * RPAD + sub * 4) * 4,
                     vt + (size_t)row * SQ + sub * 8);
            }
        }
        CP_COMMIT();
    };

    // prime the ring: tiles 0..3 (4 commit groups in flight)
    load_kv(0); load_kv(1); load_kv(2); load_kv(3);

    // ---- Q A-fragments converted in-kernel from f32 gmem (own rows only) ----
    const int r0 = qb + w * 32 + g;
    uint32_t qa[2][4][4];
    {
        const float* Qb = Qf + (size_t)b * SQ * DD;
        #pragma unroll
        for (int m = 0; m < 2; m++) {
            #pragma unroll
            for (int kb = 0; kb < 4; kb++) {
                int rr = r0 + 16 * m;
                int cf = (kb * 8 + q) * 2;            // float column
                float2 f0 = *(const float2*)(Qb + (size_t)rr * DD + cf);
                float2 f1 = *(const float2*)(Qb + (size_t)(rr + 8) * DD + cf);
                float2 f2 = *(const float2*)(Qb + (size_t)rr * DD + cf + 8);
                float2 f3 = *(const float2*)(Qb + (size_t)(rr + 8) * DD + cf + 8);
                qa[m][kb][0] = pk(f0.x * SCALE, f0.y * SCALE);
                qa[m][kb][1] = pk(f1.x * SCALE, f1.y * SCALE);
                qa[m][kb][2] = pk(f2.x * SCALE, f2.y * SCALE);
                qa[m][kb][3] = pk(f3.x * SCALE, f3.y * SCALE);
            }
        }
    }

    float o[2][8][4];
    #pragma unroll
    for (int m = 0; m < 2; m++)
        #pragma unroll
        for (int j = 0; j < 8; j++)
            #pragma unroll
            for (int i = 0; i < 4; i++) o[m][j][i] = 0.0f;

    float lacc[2][2] = {{0.f, 0.f}, {0.f, 0.f}};

    auto compute_tile = [&](int t) {
        const uint32_t* Kslot = Ks + (t % NSLOT) * SLOTW;
        const uint32_t* Vslot = Vs + (t % NSLOT) * SLOTW;

        #pragma unroll
        for (int kk = 0; kk < 4; kk++) {      // 16 keys per kk
            uint32_t pa[2][4];

            #pragma unroll
            for (int jj = 0; jj < 2; jj++) {
                const int j = kk * 2 + jj;
                float c4[2][4] = {{0.f, 0.f, 0.f, 0.f}, {0.f, 0.f, 0.f, 0.f}};
                const uint32_t* kr = Kslot + (8 * j + g) * RPAD + q;
                #pragma unroll
                for (int kb = 0; kb < 4; kb++) {
                    uint32_t b0 = kr[kb * 8];
                    uint32_t b1 = kr[kb * 8 + 4];
                    mma_f16(c4[0], qa[0][kb][0], qa[0][kb][1], qa[0][kb][2], qa[0][kb][3], b0, b1);
                    mma_f16(c4[1], qa[1][kb][0], qa[1][kb][1], qa[1][kb][2], qa[1][kb][3], b0, b1);
                }
                #pragma unroll
                for (int m = 0; m < 2; m++) {
                    float p0 = ex2(c4[m][0]);      // logits already in log2 domain
                    float p1 = ex2(c4[m][1]);
                    float p2 = ex2(c4[m][2]);
                    float p3 = ex2(c4[m][3]);
                    lacc[m][0] += p0 + p1;
                    lacc[m][1] += p2 + p3;
                    pa[m][jj * 2]     = pk(p0, p1);
                    pa[m][jj * 2 + 1] = pk(p2, p3);
                }
            }

            const uint32_t* vr = Vslot + kk * 8 + q;
            #pragma unroll
            for (int j2 = 0; j2 < 8; j2++) {
                uint32_t b0 = vr[(8 * j2 + g) * RPAD];
                uint32_t b1 = vr[(8 * j2 + g) * RPAD + 4];
                mma_f16(o[0][j2], pa[0][0], pa[0][1], pa[0][2], pa[0][3], b0, b1);
                mma_f16(o[1][j2], pa[1][0], pa[1][1], pa[1][2], pa[1][3], b0, b1);
            }
        }
    };

    // ---- pair loop: one barrier per 2 tiles ----
    for (int p = 0; p < NPAIRS; p++) {
        if (p == NPAIRS - 1) { CP_WAIT(0); } else { CP_WAIT(2); }
        __syncthreads();   // pair data visible AND pair p-1's slots fully consumed

        // refill the slots freed by the barrier (tiles 2p-2, 2p-1 -> 2p+4, 2p+5)
        if (2 * p + 4 < NTILES) load_kv(2 * p + 4);
        if (2 * p + 5 < NTILES) load_kv(2 * p + 5);

        compute_tile(2 * p);
        compute_tile(2 * p + 1);
    }

    // ---- epilogue: reduce row sums, normalize, mask, store ----
    #pragma unroll
    for (int m = 0; m < 2; m++) {
        lacc[m][0] += __shfl_xor_sync(0xffffffffu, lacc[m][0], 1);
        lacc[m][0] += __shfl_xor_sync(0xffffffffu, lacc[m][0], 2);
        lacc[m][1] += __shfl_xor_sync(0xffffffffu, lacc[m][1], 1);
        lacc[m][1] += __shfl_xor_sync(0xffffffffu, lacc[m][1], 2);

        const int row0 = r0 + 16 * m;
        const int row1 = row0 + 8;
        const float inv0 = Mask[(size_t)b * SQ + row0] / lacc[m][0];
        const float inv1 = Mask[(size_t)b * SQ + row1] / lacc[m][1];

        float* o0 = O + ((size_t)b * SQ + row0) * DD;
        float* o1 = O + ((size_t)b * SQ + row1) * DD;
        #pragma unroll
        for (int j = 0; j < 8; j++) {
            float2 v0 = make_float2(o[m][j][0] * inv0, o[m][j][1] * inv0);
            float2 v1 = make_float2(o[m][j][2] * inv1, o[m][j][3] * inv1);
            *(float2*)(o0 + 8 * j + 2 * q) = v0;
            *(float2*)(o1 + 8 * j + 2 * q) = v1;
        }
    }
}

extern "C" void kernel_launch(void* const* d_in, const int* in_sizes, int n_in,
                              void* d_out, int out_size) {
    const float* q    = (const float*)d_in[0];
    const float* k    = (const float*)d_in[1];
    const float* v    = (const float*)d_in[2];
    const float* mask = (const float*)d_in[3];
    float* out        = (float*)d_out;

    static int configured = 0;
    if (!configured) {
        cudaFuncSetAttribute(attn_mma, cudaFuncAttributeMaxDynamicSharedMemorySize, SMEM_BYTES);
        configured = 1;
    }

    cvt_all<<<NKC + NVT, 256>>>(k, v);

    dim3 grid(SQ / QT, BB);
    attn_mma<<<grid, NT, SMEM_BYTES>>>(q, mask, out);
}

// round 15
// speedup vs baseline: 1.0311x; 1.0311x over previous
#include <cuda_runtime.h>
#include <cuda_fp16.h>
#include <cstdint>

#define SQ      4096
#define DD      64
#define QT      128          // q rows per CTA
#define KT      64           // keys per tile
#define NT      128          // threads (4 warps x 32 q rows)
#define NTILES  (SQ / KT)    // 64
#define BB      8

// fp16 scratch (converted once per launch by prologue kernel)
__device__ __half g_Qh[(size_t)BB * SQ * DD];   // [b][s][d], pre-scaled
__device__ __half g_Kh[(size_t)BB * SQ * DD];   // [b][s][d]
__device__ __half g_Vt[(size_t)BB * DD * SQ];   // [b][d][s]  (transposed)

#define SCALE (0.125f * 1.44269504088896340736f)   // 1/sqrt(64) * log2(e)

#define RPAD 36   // K/V tile row: 64 halfs = 32 words + 4 pad -> conflict-free

__device__ __forceinline__ uint32_t s2u(const void* p) {
    uint32_t a;
    asm("{ .reg .u64 t; cvta.to.shared.u64 t, %1; cvt.u32.u64 %0, t; }" : "=r"(a) : "l"(p));
    return a;
}
__device__ __forceinline__ void cp16(uint32_t d, const void* s) {
    asm volatile("cp.async.cg.shared.global [%0], [%1], 16;" :: "r"(d), "l"(s));
}
#define CP_COMMIT() asm volatile("cp.async.commit_group;" ::: "memory")
#define CP_WAIT(n)  asm volatile("cp.async.wait_group %0;" :: "n"(n) : "memory")

// pack (lo=p0, hi=p1) as f16x2
__device__ __forceinline__ uint32_t pk(float p0, float p1) {
    uint32_t r;
    asm("cvt.rn.f16x2.f32 %0, %1, %2;" : "=r"(r) : "f"(p1), "f"(p0));
    return r;
}
// packed half-precision exp2: two elements per MUFU op
__device__ __forceinline__ uint32_t hex2(uint32_t x) {
    uint32_t r;
    asm("ex2.approx.f16x2 %0, %1;" : "=r"(r) : "r"(x));
    return r;
}
__device__ __forceinline__ void mma_f16(float* c, uint32_t a0, uint32_t a1, uint32_t a2,
                                        uint32_t a3, uint32_t b0, uint32_t b1) {
    asm volatile(
        "mma.sync.aligned.m16n8k16.row.col.f32.f16.f16.f32 "
        "{%0,%1,%2,%3}, {%4,%5,%6,%7}, {%8,%9}, {%0,%1,%2,%3};"
        : "+f"(c[0]), "+f"(c[1]), "+f"(c[2]), "+f"(c[3])
        : "r"(a0), "r"(a1), "r"(a2), "r"(a3), "r"(b0), "r"(b1));
}

// ---- fused prologue ----
#define NQK (BB * SQ * DD / 4 / 256)        // 2048 blocks: Q/K convert
#define NVT (BB * (SQ / 64))                // 512 blocks: V transpose

__global__ void __launch_bounds__(256)
cvt_all(const float* __restrict__ Q, const float* __restrict__ K,
        const float* __restrict__ V) {
    if (blockIdx.x < NQK) {
        int i = blockIdx.x * 256 + threadIdx.x;       // float4 index
        float4 q = ((const float4*)Q)[i];
        float4 k = ((const float4*)K)[i];
        __half2* qo = (__half2*)g_Qh;
        __half2* ko = (__half2*)g_Kh;
        qo[2 * i]     = __floats2half2_rn(q.x * SCALE, q.y * SCALE);
        qo[2 * i + 1] = __floats2half2_rn(q.z * SCALE, q.w * SCALE);
        ko[2 * i]     = __floats2half2_rn(k.x, k.y);
        ko[2 * i + 1] = __floats2half2_rn(k.z, k.w);
        return;
    }
    // ---- V transpose tile: batch b, s-range [s0, s0+64) ----
    __shared__ float tl[64][65];
    const int vb  = blockIdx.x - NQK;
    const int b   = vb >> 6;
    const int s0  = (vb & 63) * 64;
    const int tid = threadIdx.x;

    const float* src = V + ((size_t)b * SQ + s0) * DD;
    #pragma unroll
    for (int i = 0; i < 16; i++) {
        int idx = tid + i * 256;
        tl[idx >> 6][idx & 63] = src[idx];            // coalesced read
    }
    __syncthreads();

    __half* dst = g_Vt + (size_t)b * DD * SQ + s0;
    #pragma unroll
    for (int i = 0; i < 2; i++) {
        int c  = tid + i * 256;
        int d  = c >> 3;
        int sc = (c & 7) * 8;
        __half h[8];
        #pragma unroll
        for (int j = 0; j < 8; j++) h[j] = __float2half_rn(tl[sc + j][d]);
        *(uint4*)(dst + (size_t)d * SQ + sc) = *(uint4*)h;   // coalesced 16B write
    }
}

__global__ void __launch_bounds__(NT, 2)
attn_mma(const float* __restrict__ Mask, float* __restrict__ O) {
    __shared__ uint32_t Ks[2][KT * RPAD];   // keys x d(halfs)
    __shared__ uint32_t Vs[2][DD * RPAD];   // d x keys(halfs)

    const int tid  = threadIdx.x;
    const int w    = tid >> 5;
    const int lane = tid & 31;
    const int g    = lane >> 2;
    const int q    = lane & 3;

    const int b  = blockIdx.y;
    const int qb = blockIdx.x * QT;
    const __half* Kg = g_Kh + (size_t)b * SQ * DD;
    const __half* Vg = g_Vt + (size_t)b * DD * SQ;

    const uint32_t ks_u = s2u(Ks);
    const uint32_t vs_u = s2u(Vs);

    auto load_kv = [&](int tile) {
        const int slot = tile & 1;
        const __half* kt = Kg + (size_t)tile * KT * DD;
        const __half* vt = Vg + tile * KT;            // V row stride SQ
        #pragma unroll
        for (int i = 0; i < 8; i++) {
            int c = tid + i * NT;                     // 0..1023
            if (c < 512) {                            // K: 64 rows x 8 chunks
                int row = c >> 3, sub = c & 7;
                cp16(ks_u + (uint32_t)(slot * KT * RPAD + row * RPAD + sub * 4) * 4,
                     kt + row * DD + sub * 8);
            } else {                                  // V: 64 rows x 8 chunks
                int c2 = c - 512;
                int row = c2 >> 3, sub = c2 & 7;
                cp16(vs_u + (uint32_t)(slot * DD * RPAD + row * RPAD + sub * 4) * 4,
                     vt + (size_t)row * SQ + sub * 8);
            }
        }
        CP_COMMIT();
    };
    load_kv(0);

    // ---- resident Q A-fragments: 2 row-blocks x 4 k-blocks x 4 regs ----
    const int r0 = qb + w * 32 + g;
    uint32_t qa[2][4][4];
    {
        const uint32_t* Qw = (const uint32_t*)(g_Qh + (size_t)b * SQ * DD);
        #pragma unroll
        for (int m = 0; m < 2; m++) {
            #pragma unroll
            for (int kb = 0; kb < 4; kb++) {
                int rr = r0 + 16 * m;
                int col = kb * 8 + q;
                qa[m][kb][0] = Qw[rr * 32 + col];
                qa[m][kb][1] = Qw[(rr + 8) * 32 + col];
                qa[m][kb][2] = Qw[rr * 32 + col + 4];
                qa[m][kb][3] = Qw[(rr + 8) * 32 + col + 4];
            }
        }
    }

    float o[2][8][4];
    #pragma unroll
    for (int m = 0; m < 2; m++)
        #pragma unroll
        for (int j = 0; j < 8; j++)
            #pragma unroll
            for (int i = 0; i < 4; i++) o[m][j][i] = 0.0f;

    float lacc[2][2] = {{0.f, 0.f}, {0.f, 0.f}};

    for (int t = 0; t < NTILES; t++) {
        const int slot = t & 1;

        CP_WAIT(0);
        __syncthreads();      // tile t staged AND every warp done with tile t-1
        if (t + 1 < NTILES) load_kv(t + 1);

        const uint32_t* Kslot = Ks[slot];
        const uint32_t* Vslot = Vs[slot];

        #pragma unroll
        for (int kk = 0; kk < 4; kk++) {      // 16 keys per kk
            uint32_t pa[2][4];

            // ---- two QK j-blocks (8 keys each) -> P fragments in registers ----
            #pragma unroll
            for (int jj = 0; jj < 2; jj++) {
                const int j = kk * 2 + jj;
                float c4[2][4] = {{0.f, 0.f, 0.f, 0.f}, {0.f, 0.f, 0.f, 0.f}};
                const uint32_t* kr = Kslot + (8 * j + g) * RPAD + q;
                #pragma unroll
                for (int kb = 0; kb < 4; kb++) {
                    uint32_t b0 = kr[kb * 8];
                    uint32_t b1 = kr[kb * 8 + 4];
                    mma_f16(c4[0], qa[0][kb][0], qa[0][kb][1], qa[0][kb][2], qa[0][kb][3], b0, b1);
                    mma_f16(c4[1], qa[1][kb][0], qa[1][kb][1], qa[1][kb][2], qa[1][kb][3], b0, b1);
                }
                // packed softmax: scores -> f16x2 -> packed ex2 (P fragments direct)
                #pragma unroll
                for (int m = 0; m < 2; m++) {
                    pa[m][jj * 2]     = hex2(pk(c4[m][0], c4[m][1]));   // row g
                    pa[m][jj * 2 + 1] = hex2(pk(c4[m][2], c4[m][3]));   // row g+8
                }
            }

            // ---- row sums: HADD2 pair-merge, fp32 accumulate ----
            #pragma unroll
            for (int m = 0; m < 2; m++) {
                __half2 s0 = __hadd2(*(__half2*)&pa[m][0], *(__half2*)&pa[m][2]);
                __half2 s1 = __hadd2(*(__half2*)&pa[m][1], *(__half2*)&pa[m][3]);
                float2 f0 = __half22float2(s0);
                float2 f1 = __half22float2(s1);
                lacc[m][0] += f0.x + f0.y;
                lacc[m][1] += f1.x + f1.y;
            }

            // ---- O += P(kk) . V ----
            const uint32_t* vr = Vslot + kk * 8 + q;
            #pragma unroll
            for (int j2 = 0; j2 < 8; j2++) {
                uint32_t b0 = vr[(8 * j2 + g) * RPAD];
                uint32_t b1 = vr[(8 * j2 + g) * RPAD + 4];
                mma_f16(o[0][j2], pa[0][0], pa[0][1], pa[0][2], pa[0][3], b0, b1);
                mma_f16(o[1][j2], pa[1][0], pa[1][1], pa[1][2], pa[1][3], b0, b1);
            }
        }
    }

    // ---- epilogue: reduce row sums, normalize, mask, store ----
    #pragma unroll
    for (int m = 0; m < 2; m++) {
        lacc[m][0] += __shfl_xor_sync(0xffffffffu, lacc[m][0], 1);
        lacc[m][0] += __shfl_xor_sync(0xffffffffu, lacc[m][0], 2);
        lacc[m][1] += __shfl_xor_sync(0xffffffffu, lacc[m][1], 1);
        lacc[m][1] += __shfl_xor_sync(0xffffffffu, lacc[m][1], 2);

        const int row0 = r0 + 16 * m;
        const int row1 = row0 + 8;
        const float inv0 = Mask[(size_t)b * SQ + row0] / lacc[m][0];
        const float inv1 = Mask[(size_t)b * SQ + row1] / lacc[m][1];

        float* o0 = O + ((size_t)b * SQ + row0) * DD;
        float* o1 = O + ((size_t)b * SQ + row1) * DD;
        #pragma unroll
        for (int j = 0; j < 8; j++) {
            float2 v0 = make_float2(o[m][j][0] * inv0, o[m][j][1] * inv0);
            float2 v1 = make_float2(o[m][j][2] * inv1, o[m][j][3] * inv1);
            *(float2*)(o0 + 8 * j + 2 * q) = v0;
            *(float2*)(o1 + 8 * j + 2 * q) = v1;
        }
    }
}

extern "C" void kernel_launch(void* const* d_in, const int* in_sizes, int n_in,
                              void* d_out, int out_size) {
    const float* q    = (const float*)d_in[0];
    const float* k    = (const float*)d_in[1];
    const float* v    = (const float*)d_in[2];
    const float* mask = (const float*)d_in[3];
    float* out        = (float*)d_out;

    cvt_all<<<NQK + NVT, 256>>>(q, k, v);

    dim3 grid(SQ / QT, BB);
    attn_mma<<<grid, NT>>>(mask, out);
}